// round 10
// baseline (speedup 1.0000x reference)
#include <cuda_runtime.h>
#include <cuda_bf16.h>

#define EPS 1e-5f

// Scratch (device globals: allocation-free)
__device__ float g_a[256 * 32];     // a = x@W1 + b1
__device__ float g_s[256];          // row sums of a
__device__ float g_q[256];          // row sums of a^2
__device__ float g_G[32 * 1024];    // G[d][col], col = e*32+o : gamma[d*32+e]*W2[(d*32+e)*32+o]
__device__ float g_U[256 * 1024];   // U[i][col], col = e*32+o : sum_d a[i,d]*G[d][col]
__device__ float g_c[32];           // c[o] = sum_k gamma[k]*W2[k,o]
__device__ float g_t[32];           // t[o] = sum_k beta[k]*W2[k,o] + b2[o]

// ---- f32x2 packed helpers (Blackwell) ----
#define FMA_F32X2(acc, a, b) \
    asm("fma.rn.f32x2 %0, %1, %2, %3;" : "=l"(acc) : "l"(a), "l"(b), "l"(acc))
#define PACK2(out, lo, hi) \
    asm("mov.b64 %0, {%1, %2};" : "=l"(out) : "f"(lo), "f"(hi))
#define DUP2(out, v) \
    asm("mov.b64 %0, {%1, %1};" : "=l"(out) : "f"(v))
#define UNPACK2(lo, hi, in) \
    asm("mov.b64 {%0, %1}, %2;" : "=f"(lo), "=f"(hi) : "l"(in))

// ---------------------------------------------------------------------------
// k0: blocks 0..31  -> a = x@W1 + b1 for 8 rows each, publish a/s/q
//     blocks 32..63 -> G[d][e*32+o] = gamma[d*32+e] * W2[(d*32+e)*32+o]
//     block 64      -> c[o], t[o]
// ---------------------------------------------------------------------------
__global__ __launch_bounds__(256) void k0(const float* __restrict__ x,
                                          const float* __restrict__ W1,
                                          const float* __restrict__ b1,
                                          const float* __restrict__ gamma,
                                          const float* __restrict__ beta,
                                          const float* __restrict__ W2,
                                          const float* __restrict__ b2) {
    int bx = blockIdx.x;
    int tid = threadIdx.x;

    if (bx < 32) {
        int i0 = bx * 8;
        __shared__ __align__(16) float xs[8 * 256];
        __shared__ float red[8][8][32];
        {
            const float4* xp = (const float4*)(x + i0 * 256);
            float4* sp = (float4*)xs;
            sp[tid]       = xp[tid];
            sp[tid + 256] = xp[tid + 256];
        }
        __syncthreads();

        int h = tid & 31, grp = tid >> 5;
        {
            float acc[8];
#pragma unroll
            for (int r = 0; r < 8; r++) acc[r] = 0.f;
#pragma unroll
            for (int cc = 0; cc < 8; cc++) {
                int c = grp * 32 + cc * 4;
                float w0 = W1[(c + 0) * 32 + h];
                float w1 = W1[(c + 1) * 32 + h];
                float w2 = W1[(c + 2) * 32 + h];
                float w3 = W1[(c + 3) * 32 + h];
#pragma unroll
                for (int r = 0; r < 8; r++) {
                    float4 xv = *(const float4*)&xs[r * 256 + c];
                    acc[r] += xv.x * w0 + xv.y * w1 + xv.z * w2 + xv.w * w3;
                }
            }
#pragma unroll
            for (int r = 0; r < 8; r++) red[grp][r][h] = acc[r];
        }
        __syncthreads();
        {
            int r = tid >> 5;
            float a = b1[h];
#pragma unroll
            for (int g = 0; g < 8; g++) a += red[g][r][h];
            g_a[(i0 + r) * 32 + h] = a;
            float s = a, q = a * a;
#pragma unroll
            for (int off = 16; off; off >>= 1) {
                s += __shfl_down_sync(0xffffffffu, s, off);
                q += __shfl_down_sync(0xffffffffu, q, off);
            }
            if (h == 0) { g_s[i0 + r] = s; g_q[i0 + r] = q; }
        }
    } else if (bx < 64) {
        int d = bx - 32;
        int col0 = tid * 4;
        int e = col0 >> 5, o = col0 & 31;      // 4 consecutive cols: same e, o..o+3
        float ga = gamma[d * 32 + e];
        float4 w = *(const float4*)&W2[(d * 32 + e) * 32 + o];
        float4 r = make_float4(ga * w.x, ga * w.y, ga * w.z, ga * w.w);
        *(float4*)&g_G[d * 1024 + col0] = r;
    } else {
        __shared__ float rc[8][32], rt[8][32];
        int o = tid & 31, grp = tid >> 5;
        float pc = 0.f, pt = 0.f;
        int k0i = grp * 128;
#pragma unroll 8
        for (int k = k0i; k < k0i + 128; k++) {
            float w = W2[k * 32 + o];
            pc += gamma[k] * w;
            pt += beta[k] * w;
        }
        rc[grp][o] = pc;
        rt[grp][o] = pt;
        __syncthreads();
        if (tid < 32) {
            float cc = 0.f, tt = b2[o];
#pragma unroll
            for (int g = 0; g < 8; g++) { cc += rc[g][o]; tt += rt[g][o]; }
            g_c[o] = cc;
            g_t[o] = tt;
        }
    }
}

// ---------------------------------------------------------------------------
// k2: U[i][col] = sum_d a[i][d] * G[d][col]. Grid 128 = 32 i-tiles x 4 col-tiles.
// G tile staged in smem (coalesced), a pre-packed into f32x2 row pairs.
// ---------------------------------------------------------------------------
__global__ __launch_bounds__(256) void k2(void) {
    __shared__ __align__(16) float Gs[32 * 256];              // 32 KB
    __shared__ __align__(16) unsigned long long as2[4][32];   // packed (a[2r],a[2r+1])

    int tid = threadIdx.x;
    int it = blockIdx.x >> 2, ct = blockIdx.x & 3;
    int i0 = it * 8;

    {
        const float4* gp = (const float4*)g_G;
        float4* sp = (float4*)Gs;
#pragma unroll
        for (int k = 0; k < 8; k++) {
            int f = tid + k * 256;            // float4 idx within tile [0,2048)
            int d = f >> 6, cc = f & 63;
            sp[f] = gp[d * 256 + ct * 64 + cc];
        }
    }
    if (tid < 128) {
        int r2 = tid >> 5, dd = tid & 31;
        float a0 = g_a[(i0 + 2 * r2) * 32 + dd];
        float a1 = g_a[(i0 + 2 * r2 + 1) * 32 + dd];
        unsigned long long v;
        PACK2(v, a0, a1);
        as2[r2][dd] = v;
    }
    __syncthreads();

    int col = ct * 256 + tid;
    float g[32];
#pragma unroll
    for (int d = 0; d < 32; d++) g[d] = Gs[d * 256 + tid];   // lane-consecutive

    unsigned long long acc[4] = {0ull, 0ull, 0ull, 0ull};
#pragma unroll
    for (int d = 0; d < 32; d++) {
        unsigned long long gd;
        DUP2(gd, g[d]);
#pragma unroll
        for (int r2 = 0; r2 < 4; r2++)
            FMA_F32X2(acc[r2], as2[r2][d], gd);              // broadcast LDS.64
    }
#pragma unroll
    for (int r2 = 0; r2 < 4; r2++) {
        float a0, a1;
        UNPACK2(a0, a1, acc[r2]);
        g_U[(i0 + 2 * r2) * 1024 + col]     = a0;
        g_U[(i0 + 2 * r2 + 1) * 1024 + col] = a1;
    }
}

// ---------------------------------------------------------------------------
// k3: out[i,j,o] = P_ij*(sum_e U[i,e,o]*a[j,e]) + (t[o] - Q_ij*c[o])
// Grid (8 j-chunks of 32, 64 i-tiles of 4), 128 thr = 32 o x 4 jslot.
// Thread: acc[4 i][4 jp] = 16 independent FFMA2 chains; U via smem (conflict-
// free scalar LDS, lanes=o); b pairs via broadcast LDS.128 in 4-e chunks.
// ---------------------------------------------------------------------------
__global__ __launch_bounds__(128) void k3(float* __restrict__ out) {
    __shared__ __align__(16) float Us[4 * 1024];               // 16 KB, [i][e*32+o]
    __shared__ __align__(16) unsigned long long ajp[16][32];   // 4 KB
    __shared__ __align__(16) float pq[4][16][4];               // 1 KB

    int tid = threadIdx.x;
    int j0 = blockIdx.x * 32, i0 = blockIdx.y * 4;

    {
        const float4* up = (const float4*)(g_U + (size_t)i0 * 1024);
        float4* sp = (float4*)Us;
#pragma unroll
        for (int k = 0; k < 8; k++) sp[tid + k * 128] = up[tid + k * 128];
    }
#pragma unroll
    for (int k = 0; k < 4; k++) {
        int idx = tid + k * 128;
        int jp = idx >> 5, e = idx & 31;
        float a0 = g_a[(j0 + 2 * jp) * 32 + e];
        float a1 = g_a[(j0 + 2 * jp + 1) * 32 + e];
        unsigned long long v;
        PACK2(v, a0, a1);
        ajp[jp][e] = v;
    }
    if (tid < 64) {
        int il = tid >> 4, jp = tid & 15;
        const float inv = 1.0f / 1024.0f;
        float si = g_s[i0 + il] * inv, qi = g_q[i0 + il] * inv;
        float4 v;
        int j = j0 + 2 * jp;
        float mu = si * g_s[j];
        float var = qi * g_q[j] - mu * mu;
        float r = rsqrtf(var + EPS);
        v.x = r; v.z = r * mu;
        j++;
        mu = si * g_s[j];
        var = qi * g_q[j] - mu * mu;
        r = rsqrtf(var + EPS);
        v.y = r; v.w = r * mu;
        *(float4*)&pq[il][jp][0] = v;
    }
    __syncthreads();

    int o = tid & 31, jslot = tid >> 5;
    float co = g_c[o], to = g_t[o];

    unsigned long long acc[4][4];
#pragma unroll
    for (int i = 0; i < 4; i++)
#pragma unroll
        for (int jp = 0; jp < 4; jp++) acc[i][jp] = 0ull;

#pragma unroll
    for (int ec = 0; ec < 8; ec++) {       // 4 e per chunk
        unsigned long long bb[4][4];
#pragma unroll
        for (int jp = 0; jp < 4; jp++) {
            const ulonglong2* bp = (const ulonglong2*)&ajp[jslot * 4 + jp][ec * 4];
            ulonglong2 b01 = bp[0], b23 = bp[1];  // broadcast LDS.128
            bb[jp][0] = b01.x; bb[jp][1] = b01.y;
            bb[jp][2] = b23.x; bb[jp][3] = b23.y;
        }
#pragma unroll
        for (int i = 0; i < 4; i++) {
#pragma unroll
            for (int e = 0; e < 4; e++) {
                float u = Us[i * 1024 + (ec * 4 + e) * 32 + o];
                unsigned long long uu;
                DUP2(uu, u);
                FMA_F32X2(acc[i][0], uu, bb[0][e]);
                FMA_F32X2(acc[i][1], uu, bb[1][e]);
                FMA_F32X2(acc[i][2], uu, bb[2][e]);
                FMA_F32X2(acc[i][3], uu, bb[3][e]);
            }
        }
    }

#pragma unroll
    for (int i = 0; i < 4; i++) {
        float* op = out + ((size_t)(i0 + i) * 256 + j0 + jslot * 8) * 32 + o;
#pragma unroll
        for (int jp = 0; jp < 4; jp++) {
            float4 v = *(const float4*)&pq[i][jslot * 4 + jp][0];  // warp-uniform
            float a0, a1;
            UNPACK2(a0, a1, acc[i][jp]);
            op[(size_t)(2 * jp) * 32]     = v.x * a0 + (to - v.z * co);
            op[(size_t)(2 * jp + 1) * 32] = v.y * a1 + (to - v.w * co);
        }
    }
}

extern "C" void kernel_launch(void* const* d_in, const int* in_sizes, int n_in,
                              void* d_out, int out_size) {
    const float* x     = (const float*)d_in[0];
    const float* W1    = (const float*)d_in[1];
    const float* b1    = (const float*)d_in[2];
    const float* gamma = (const float*)d_in[3];
    const float* beta  = (const float*)d_in[4];
    const float* W2    = (const float*)d_in[5];
    const float* b2    = (const float*)d_in[6];
    float* out = (float*)d_out;

    k0<<<65, 256>>>(x, W1, b1, gamma, beta, W2, b2);
    k2<<<128, 256>>>();
    k3<<<dim3(8, 64), 128>>>(out);
}

// round 12
// speedup vs baseline: 1.1345x; 1.1345x over previous
#include <cuda_runtime.h>
#include <cuda_bf16.h>

#define EPS 1e-5f

// Scratch (device globals: allocation-free)
__device__ float g_a[256 * 32];     // a = x@W1 + b1
__device__ float g_s[256];          // row sums of a
__device__ float g_q[256];          // row sums of a^2
__device__ float g_U[256 * 1024];   // U[i][col], col = e*32+o : sum_d a[i,d]*G[d][col]
__device__ float g_c[32];           // c[o] = sum_k gamma[k]*W2[k,o]
__device__ float g_t[32];           // t[o] = sum_k beta[k]*W2[k,o] + b2[o]

// ---- f32x2 packed helpers (Blackwell) ----
#define FMA_F32X2(acc, a, b) \
    asm("fma.rn.f32x2 %0, %1, %2, %3;" : "=l"(acc) : "l"(a), "l"(b), "l"(acc))
#define PACK2(out, lo, hi) \
    asm("mov.b64 %0, {%1, %2};" : "=l"(out) : "f"(lo), "f"(hi))
#define DUP2(out, v) \
    asm("mov.b64 %0, {%1, %1};" : "=l"(out) : "f"(v))
#define UNPACK2(lo, hi, in) \
    asm("mov.b64 {%0, %1}, %2;" : "=f"(lo), "=f"(hi) : "l"(in))

// ---------------------------------------------------------------------------
// kA: fused front end, ONE launch.
//   blocks 0..127: it = bx>>2 (8-row i-tile), ct = bx&3 (256-col U tile).
//     Phase 1: a = x@W1 + b1 for the 8 rows (publish a/s/q when ct==0).
//     Phase 2: per-thread g[d] = gamma[d*32+e]*W2[(d*32+e)*32+o]  (coalesced:
//              warp lanes = consecutive o at fixed e).
//     Phase 3: U rows via f32x2 over packed row-pairs.
//   block 128: c[o], t[o].
// ---------------------------------------------------------------------------
__global__ __launch_bounds__(256) void kA(const float* __restrict__ x,
                                          const float* __restrict__ W1,
                                          const float* __restrict__ b1,
                                          const float* __restrict__ gamma,
                                          const float* __restrict__ beta,
                                          const float* __restrict__ W2,
                                          const float* __restrict__ b2) {
    int bx = blockIdx.x;
    int tid = threadIdx.x;

    if (bx == 128) {
        __shared__ float rc[8][32], rt[8][32];
        int o = tid & 31, grp = tid >> 5;
        float pc = 0.f, pt = 0.f;
        int k0i = grp * 128;
#pragma unroll 8
        for (int k = k0i; k < k0i + 128; k++) {
            float w = W2[k * 32 + o];
            pc += gamma[k] * w;
            pt += beta[k] * w;
        }
        rc[grp][o] = pc;
        rt[grp][o] = pt;
        __syncthreads();
        if (tid < 32) {
            float cc = 0.f, tt = b2[o];
#pragma unroll
            for (int g = 0; g < 8; g++) { cc += rc[g][o]; tt += rt[g][o]; }
            g_c[o] = cc;
            g_t[o] = tt;
        }
        return;
    }

    int it = bx >> 2, ct = bx & 3;
    int i0 = it * 8;

    __shared__ __align__(16) float xs[8 * 256];               // 8 KB
    __shared__ float red[8][8][32];                           // 8 KB
    __shared__ __align__(16) unsigned long long as2[4][32];   // packed (a[2r],a[2r+1])

    // Load x rows i0..i0+7 via float4
    {
        const float4* xp = (const float4*)(x + i0 * 256);
        float4* sp = (float4*)xs;
        sp[tid]       = xp[tid];
        sp[tid + 256] = xp[tid + 256];
    }
    __syncthreads();

    int h = tid & 31, grp = tid >> 5;
    {
        float acc[8];
#pragma unroll
        for (int r = 0; r < 8; r++) acc[r] = 0.f;
#pragma unroll
        for (int cc = 0; cc < 8; cc++) {
            int c = grp * 32 + cc * 4;
            float w0 = W1[(c + 0) * 32 + h];
            float w1 = W1[(c + 1) * 32 + h];
            float w2 = W1[(c + 2) * 32 + h];
            float w3 = W1[(c + 3) * 32 + h];
#pragma unroll
            for (int r = 0; r < 8; r++) {
                float4 xv = *(const float4*)&xs[r * 256 + c];
                acc[r] += xv.x * w0 + xv.y * w1 + xv.z * w2 + xv.w * w3;
            }
        }
#pragma unroll
        for (int r = 0; r < 8; r++) red[grp][r][h] = acc[r];
    }
    __syncthreads();

    // Reduce partials -> a; publish; pack row-pairs for the U loop
    {
        int r = tid >> 5;
        float a = b1[h];
#pragma unroll
        for (int g = 0; g < 8; g++) a += red[g][r][h];
        if (ct == 0) g_a[(i0 + r) * 32 + h] = a;
        // pack (a[2r2], a[2r2+1]) lanes: thread with even r writes lo, odd hi
        // simpler: write scalar then repack below from red reuse — use xs as temp
        xs[r * 32 + h] = a;
        float s = a, q = a * a;
#pragma unroll
        for (int off = 16; off; off >>= 1) {
            s += __shfl_down_sync(0xffffffffu, s, off);
            q += __shfl_down_sync(0xffffffffu, q, off);
        }
        if (ct == 0 && h == 0) { g_s[i0 + r] = s; g_q[i0 + r] = q; }
    }
    __syncthreads();
    if (tid < 128) {
        int r2 = tid >> 5, dd = tid & 31;
        unsigned long long v;
        PACK2(v, xs[(2 * r2) * 32 + dd], xs[(2 * r2 + 1) * 32 + dd]);
        as2[r2][dd] = v;
    }
    __syncthreads();

    // g[d] build (coalesced) + U f32x2
    {
        int col = ct * 256 + tid;
        int e = col >> 5, o = col & 31;
        float g[32];
#pragma unroll
        for (int d = 0; d < 32; d++)
            g[d] = gamma[d * 32 + e] * W2[(d * 32 + e) * 32 + o];

        unsigned long long acc2[4] = {0ull, 0ull, 0ull, 0ull};
#pragma unroll
        for (int d = 0; d < 32; d++) {
            unsigned long long gd;
            DUP2(gd, g[d]);
#pragma unroll
            for (int r2 = 0; r2 < 4; r2++)
                FMA_F32X2(acc2[r2], as2[r2][d], gd);
        }
#pragma unroll
        for (int r2 = 0; r2 < 4; r2++) {
            float a0, a1;
            UNPACK2(a0, a1, acc2[r2]);
            g_U[(i0 + 2 * r2) * 1024 + col]     = a0;
            g_U[(i0 + 2 * r2 + 1) * 1024 + col] = a1;
        }
    }
}

// ---------------------------------------------------------------------------
// k3: out[i,j,o] = P_ij*(sum_e U[i,e,o]*a[j,e]) + (t[o] - Q_ij*c[o])
// Grid (8 j-chunks of 32, 64 i-tiles of 4), 128 thr = 32 o x 4 jslot.
// Thread: acc[4 i][4 jp] = 16 independent FFMA2 chains; U via smem scalar LDS
// (lanes=o, conflict-free); b pairs via broadcast LDS.128 in 4-e chunks.
// ---------------------------------------------------------------------------
__global__ __launch_bounds__(128) void k3(float* __restrict__ out) {
    __shared__ __align__(16) float Us[4 * 1024];               // 16 KB, [i][e*32+o]
    __shared__ __align__(16) unsigned long long ajp[16][32];   // 4 KB
    __shared__ __align__(16) float pq[4][16][4];               // 1 KB

    int tid = threadIdx.x;
    int j0 = blockIdx.x * 32, i0 = blockIdx.y * 4;

    {
        const float4* up = (const float4*)(g_U + (size_t)i0 * 1024);
        float4* sp = (float4*)Us;
#pragma unroll
        for (int k = 0; k < 8; k++) sp[tid + k * 128] = up[tid + k * 128];
    }
#pragma unroll
    for (int k = 0; k < 4; k++) {
        int idx = tid + k * 128;
        int jp = idx >> 5, e = idx & 31;
        float a0 = g_a[(j0 + 2 * jp) * 32 + e];
        float a1 = g_a[(j0 + 2 * jp + 1) * 32 + e];
        unsigned long long v;
        PACK2(v, a0, a1);
        ajp[jp][e] = v;
    }
    if (tid < 64) {
        int il = tid >> 4, jp = tid & 15;
        const float inv = 1.0f / 1024.0f;
        float si = g_s[i0 + il] * inv, qi = g_q[i0 + il] * inv;
        float4 v;
        int j = j0 + 2 * jp;
        float mu = si * g_s[j];
        float var = qi * g_q[j] - mu * mu;
        float r = rsqrtf(var + EPS);
        v.x = r; v.z = r * mu;
        j++;
        mu = si * g_s[j];
        var = qi * g_q[j] - mu * mu;
        r = rsqrtf(var + EPS);
        v.y = r; v.w = r * mu;
        *(float4*)&pq[il][jp][0] = v;
    }
    __syncthreads();

    int o = tid & 31, jslot = tid >> 5;
    float co = g_c[o], to = g_t[o];

    unsigned long long acc[4][4];
#pragma unroll
    for (int i = 0; i < 4; i++)
#pragma unroll
        for (int jp = 0; jp < 4; jp++) acc[i][jp] = 0ull;

#pragma unroll
    for (int ec = 0; ec < 8; ec++) {       // 4 e per chunk
        unsigned long long bb[4][4];
#pragma unroll
        for (int jp = 0; jp < 4; jp++) {
            const ulonglong2* bp = (const ulonglong2*)&ajp[jslot * 4 + jp][ec * 4];
            ulonglong2 b01 = bp[0], b23 = bp[1];  // broadcast LDS.128
            bb[jp][0] = b01.x; bb[jp][1] = b01.y;
            bb[jp][2] = b23.x; bb[jp][3] = b23.y;
        }
#pragma unroll
        for (int i = 0; i < 4; i++) {
#pragma unroll
            for (int e = 0; e < 4; e++) {
                float u = Us[i * 1024 + (ec * 4 + e) * 32 + o];
                unsigned long long uu;
                DUP2(uu, u);
                FMA_F32X2(acc[i][0], uu, bb[0][e]);
                FMA_F32X2(acc[i][1], uu, bb[1][e]);
                FMA_F32X2(acc[i][2], uu, bb[2][e]);
                FMA_F32X2(acc[i][3], uu, bb[3][e]);
            }
        }
    }

#pragma unroll
    for (int i = 0; i < 4; i++) {
        float* op = out + ((size_t)(i0 + i) * 256 + j0 + jslot * 8) * 32 + o;
#pragma unroll
        for (int jp = 0; jp < 4; jp++) {
            float4 v = *(const float4*)&pq[i][jslot * 4 + jp][0];  // warp-uniform
            float a0, a1;
            UNPACK2(a0, a1, acc[i][jp]);
            op[(size_t)(2 * jp) * 32]     = v.x * a0 + (to - v.z * co);
            op[(size_t)(2 * jp + 1) * 32] = v.y * a1 + (to - v.w * co);
        }
    }
}

extern "C" void kernel_launch(void* const* d_in, const int* in_sizes, int n_in,
                              void* d_out, int out_size) {
    const float* x     = (const float*)d_in[0];
    const float* W1    = (const float*)d_in[1];
    const float* b1    = (const float*)d_in[2];
    const float* gamma = (const float*)d_in[3];
    const float* beta  = (const float*)d_in[4];
    const float* W2    = (const float*)d_in[5];
    const float* b2    = (const float*)d_in[6];
    float* out = (float*)d_out;

    kA<<<129, 256>>>(x, W1, b1, gamma, beta, W2, b2);
    k3<<<dim3(8, 64), 128>>>(out);
}